// round 14
// baseline (speedup 1.0000x reference)
#include <cuda_runtime.h>
#include <cuda_fp16.h>
#include <mma.h>
#include <cstdint>

using namespace nvcuda;

// Problem constants
#define BATCH 4096
#define NB    64
#define IB    256
#define OB    256
#define DIN   16384
#define DOUT  16384

// GEMM tiling: CTA 128x256, warp tile 64x64 (2x4 warps)
#define BM      128
#define BN      256
#define BK      32
#define THREADS 256
#define LDAH    40                      // halves per smem row (32 + 8 pad) -> 80B stride
#define LDC     264                     // floats per C-staging row (256 + 8 pad)

#define A_STAGE_BYTES (BM * LDAH * 2)   // 10240
#define B_STAGE_BYTES (BN * LDAH * 2)   // 20480
#define NSTAGES       (IB / BK)         // 8

// smem: [ A0 | A1 | B0 | B1 | B2 ]  aliased by C staging
#define SMEM_LOAD_BYTES (2 * A_STAGE_BYTES + 3 * B_STAGE_BYTES)   // 81920
#define C_BYTES         (BM * LDC * 4)                            // 135168
#define SMEM_TOTAL      (C_BYTES > SMEM_LOAD_BYTES ? C_BYTES : SMEM_LOAD_BYTES)

// fp16 weight copy (filled by prepass each launch; deterministic)
__device__ __half w16_g[NB * OB * IB];   // 8 MB

__device__ __forceinline__ void cp16(uint32_t s, const void* g) {
    asm volatile("cp.async.cg.shared.global [%0], [%1], 16;\n" :: "r"(s), "l"(g));
}

// ---------------- Prepass: weight fp32 -> fp16 ----------------
__global__ void convert_w_kernel(const float* __restrict__ w) {
    int idx = blockIdx.x * blockDim.x + threadIdx.x;   // 0 .. 524287
    const float4* src = (const float4*)(w) + idx * 2;
    float4 a = src[0], b = src[1];
    half2 h[4];
    h[0] = __floats2half2_rn(a.x, a.y);
    h[1] = __floats2half2_rn(a.z, a.w);
    h[2] = __floats2half2_rn(b.x, b.y);
    h[3] = __floats2half2_rn(b.z, b.w);
    *((uint4*)(w16_g) + idx) = *(const uint4*)h;
}

// ---------------- Main GEMM ----------------
__global__ __launch_bounds__(THREADS, 1)
void block_linear_fp16_kernel(const float* __restrict__ x,
                              const float* __restrict__ bias,
                              float* __restrict__ out)
{
    extern __shared__ char smem[];
    half*  sA[2] = { (half*)(smem), (half*)(smem + A_STAGE_BYTES) };
    half*  sB[3] = { (half*)(smem + 2 * A_STAGE_BYTES),
                     (half*)(smem + 2 * A_STAGE_BYTES + B_STAGE_BYTES),
                     (half*)(smem + 2 * A_STAGE_BYTES + 2 * B_STAGE_BYTES) };
    float* sC    = (float*)smem;
    const uint32_t sBu[3] = { (uint32_t)__cvta_generic_to_shared(sB[0]),
                              (uint32_t)__cvta_generic_to_shared(sB[1]),
                              (uint32_t)__cvta_generic_to_shared(sB[2]) };

    const int tid   = threadIdx.x;
    const int wid   = tid >> 5;
    const int mtile = blockIdx.x;          // 0..31
    const int nb    = blockIdx.y;          // 0..63

    const int warp_m = wid & 1;            // 2 x 64 rows
    const int warp_n = wid >> 1;           // 4 x 64 cols

    const float* xBase = x + (size_t)mtile * BM * DIN + (size_t)nb * IB;
    const half*  wBase = w16_g + (size_t)nb * OB * IB;

    // A: 128 rows x 8 float4 = 1024 -> 4 per thread
    int aR[4], aC[4];
    #pragma unroll
    for (int v = 0; v < 4; v++) { int lin = v * THREADS + tid; aR[v] = lin >> 3; aC[v] = lin & 7; }
    // B cp.async: 256 rows x 4 x 16B chunks = 1024 -> 4 per thread
    int bN[4], bC[4];
    #pragma unroll
    for (int v = 0; v < 4; v++) { int lin = v * THREADS + tid; bN[v] = lin >> 2; bC[v] = lin & 3; }

    wmma::fragment<wmma::accumulator, 16, 16, 16, float> acc[4][4];
    #pragma unroll
    for (int i = 0; i < 4; i++)
        #pragma unroll
        for (int j = 0; j < 4; j++)
            wmma::fill_fragment(acc[i][j], 0.0f);

    // ---- Prologue: issue B stages 0,1; fill A stage 0 ----
    #pragma unroll
    for (int st = 0; st < 2; st++) {
        #pragma unroll
        for (int v = 0; v < 4; v++)
            cp16(sBu[st] + bN[v] * 80 + bC[v] * 16,
                 wBase + (size_t)bN[v] * IB + st * BK + bC[v] * 8);
        asm volatile("cp.async.commit_group;\n" ::: "memory");
    }
    float4 ra[4];
    #pragma unroll
    for (int v = 0; v < 4; v++)
        ra[v] = *(const float4*)(xBase + (size_t)aR[v] * DIN + aC[v] * 4);
    #pragma unroll
    for (int v = 0; v < 4; v++) {
        half2* p = (half2*)&sA[0][aR[v] * LDAH + aC[v] * 4];
        p[0] = __floats2half2_rn(ra[v].x, ra[v].y);
        p[1] = __floats2half2_rn(ra[v].z, ra[v].w);
    }
    asm volatile("cp.async.wait_group 1;\n" ::: "memory");   // B0 arrived
    __syncthreads();

    // ---- Mainloop ----
    #pragma unroll
    for (int it = 0; it < NSTAGES; it++) {
        const int s2 = it & 1;
        const int s3 = it % 3;

        // Prefetch next A into registers (overlaps MMA)
        if (it + 1 < NSTAGES) {
            const int k0 = (it + 1) * BK;
            #pragma unroll
            for (int v = 0; v < 4; v++)
                ra[v] = *(const float4*)(xBase + (size_t)aR[v] * DIN + k0 + aC[v] * 4);
        }

        // Compute: 2 x k16 steps, warp tile 64x64 -> 16 MMAs per step
        #pragma unroll
        for (int kk = 0; kk < BK; kk += 16) {
            wmma::fragment<wmma::matrix_a, 16, 16, 16, half, wmma::row_major> af[4];
            #pragma unroll
            for (int i = 0; i < 4; i++)
                wmma::load_matrix_sync(af[i], &sA[s2][(warp_m * 64 + i * 16) * LDAH + kk], LDAH);
            #pragma unroll
            for (int j = 0; j < 4; j++) {
                wmma::fragment<wmma::matrix_b, 16, 16, 16, half, wmma::col_major> bf;
                wmma::load_matrix_sync(bf, &sB[s3][(warp_n * 64 + j * 16) * LDAH + kk], LDAH);
                #pragma unroll
                for (int i = 0; i < 4; i++)
                    wmma::mma_sync(acc[i][j], af[i], bf, acc[i][j]);
            }
        }

        if (it + 1 < NSTAGES) {
            // Convert + store next A stage
            #pragma unroll
            for (int v = 0; v < 4; v++) {
                half2* p = (half2*)&sA[s2 ^ 1][aR[v] * LDAH + aC[v] * 4];
                p[0] = __floats2half2_rn(ra[v].x, ra[v].y);
                p[1] = __floats2half2_rn(ra[v].z, ra[v].w);
            }
            // Issue B for it+2 into stage (it+2)%3 (that buffer was consumed at it-1)
            if (it + 2 < NSTAGES) {
                const int st = (it + 2) % 3;
                const int k0 = (it + 2) * BK;
                #pragma unroll
                for (int v = 0; v < 4; v++)
                    cp16(sBu[st] + bN[v] * 80 + bC[v] * 16,
                         wBase + (size_t)bN[v] * IB + k0 + bC[v] * 8);
                asm volatile("cp.async.commit_group;\n" ::: "memory");
                asm volatile("cp.async.wait_group 1;\n" ::: "memory");  // B(it+1) arrived
            } else {
                asm volatile("cp.async.wait_group 0;\n" ::: "memory");
            }
            __syncthreads();
        }
    }

    // ---- Epilogue: stage C through shared (aliases load buffers) ----
    __syncthreads();
    #pragma unroll
    for (int i = 0; i < 4; i++)
        #pragma unroll
        for (int j = 0; j < 4; j++)
            wmma::store_matrix_sync(&sC[(warp_m * 64 + i * 16) * LDC + warp_n * 64 + j * 16],
                                    acc[i][j], LDC, wmma::mem_row_major);
    __syncthreads();

    const float* biasBase = bias + (size_t)nb * OB;
    float* outBase = out + (size_t)(mtile * BM) * DOUT + (size_t)nb * OB;

    // 128 rows x 64 float4 = 8192 -> 32 per thread
    #pragma unroll
    for (int v = 0; v < 32; v++) {
        int lin = v * THREADS + tid;
        int r   = lin >> 6;       // 0..127
        int c4  = lin & 63;       // 0..63
        float4 val = *(float4*)(&sC[r * LDC + c4 * 4]);
        float4 bv  = *(const float4*)(biasBase + c4 * 4);
        val.x += bv.x; val.y += bv.y; val.z += bv.z; val.w += bv.w;
        *(float4*)(outBase + (size_t)r * DOUT + c4 * 4) = val;
    }
}

extern "C" void kernel_launch(void* const* d_in, const int* in_sizes, int n_in,
                              void* d_out, int out_size)
{
    const float* x    = (const float*)d_in[0];
    const float* w    = (const float*)d_in[1];
    const float* bias = (const float*)d_in[2];
    float* out        = (float*)d_out;

    cudaFuncSetAttribute(block_linear_fp16_kernel,
                         cudaFuncAttributeMaxDynamicSharedMemorySize, SMEM_TOTAL);

    // Prepass: convert weights to fp16
    convert_w_kernel<<<2048, 256>>>(w);

    dim3 grid(BATCH / BM, NB);   // (32, 64) = 2048 CTAs
    block_linear_fp16_kernel<<<grid, THREADS, SMEM_TOTAL>>>(x, bias, out);
}

// round 16
// speedup vs baseline: 1.4051x; 1.4051x over previous
#include <cuda_runtime.h>
#include <cuda_fp16.h>
#include <mma.h>
#include <cstdint>

using namespace nvcuda;

// Problem constants
#define BATCH 4096
#define NB    64
#define IB    256
#define OB    256
#define DIN   16384
#define DOUT  16384

// GEMM tiling (R12 shape): CTA 128x128, warp tile 32x64 (4x2 warps)
#define BM      128
#define BN      128
#define BK      32
#define THREADS 256
#define LDAH    40                      // halves per A16/B row (32+8 pad) -> 80B stride
#define LDC     136                     // floats per C-staging row (128+8 pad)

#define A32_STRIDE 144                  // bytes per A32 row (128 data + 16 pad)
#define A32_STAGE  (BM * A32_STRIDE)    // 18432
#define A16_STAGE  (BM * LDAH * 2)      // 10240
#define B_STAGE    (BN * LDAH * 2)      // 10240

// smem: A32[3] | A16[2] | B[3]  (C staging aliases from 0)
#define OFF_A32 0
#define OFF_A16 (3 * A32_STAGE)                    // 55296
#define OFF_B   (OFF_A16 + 2 * A16_STAGE)          // 75776
#define SMEM_TOTAL (OFF_B + 3 * B_STAGE)           // 106496 (C needs 69632, fits)

#define NSTAGES (IB / BK)   // 8

// fp16 weight copy (filled by prepass each launch; deterministic)
__device__ __half w16_g[NB * OB * IB];   // 8 MB

__device__ __forceinline__ void cp16(uint32_t s, const void* g) {
    asm volatile("cp.async.cg.shared.global [%0], [%1], 16;\n" :: "r"(s), "l"(g));
}
#define COMMIT() asm volatile("cp.async.commit_group;\n" ::: "memory")
#define WAITG0() asm volatile("cp.async.wait_group 0;\n" ::: "memory")
#define WAITG1() asm volatile("cp.async.wait_group 1;\n" ::: "memory")

// ---------------- Prepass: weight fp32 -> fp16 ----------------
__global__ void convert_w_kernel(const float* __restrict__ w) {
    int idx = blockIdx.x * blockDim.x + threadIdx.x;   // 0 .. 524287
    const float4* src = (const float4*)(w) + idx * 2;
    float4 a = src[0], b = src[1];
    half2 h[4];
    h[0] = __floats2half2_rn(a.x, a.y);
    h[1] = __floats2half2_rn(a.z, a.w);
    h[2] = __floats2half2_rn(b.x, b.y);
    h[3] = __floats2half2_rn(b.z, b.w);
    *((uint4*)(w16_g) + idx) = *(const uint4*)h;
}

// In-smem A convert: 128x32 fp32 -> fp16. 256 threads, 16 elems each.
__device__ __forceinline__ void convertA(const char* a32, char* a16, int tid) {
    const int row = tid >> 1, hf = tid & 1;
    const float4* src = (const float4*)(a32 + row * A32_STRIDE + hf * 64);
    float4 f0 = src[0], f1 = src[1], f2 = src[2], f3 = src[3];
    half2 h[8];
    h[0] = __floats2half2_rn(f0.x, f0.y); h[1] = __floats2half2_rn(f0.z, f0.w);
    h[2] = __floats2half2_rn(f1.x, f1.y); h[3] = __floats2half2_rn(f1.z, f1.w);
    h[4] = __floats2half2_rn(f2.x, f2.y); h[5] = __floats2half2_rn(f2.z, f2.w);
    h[6] = __floats2half2_rn(f3.x, f3.y); h[7] = __floats2half2_rn(f3.z, f3.w);
    uint4* dst = (uint4*)(a16 + row * 80 + hf * 32);
    dst[0] = *(uint4*)&h[0];
    dst[1] = *(uint4*)&h[4];
}

// ---------------- Main GEMM ----------------
__global__ __launch_bounds__(THREADS, 2)
void block_linear_fp16_kernel(const float* __restrict__ x,
                              const float* __restrict__ bias,
                              float* __restrict__ out)
{
    extern __shared__ char smem[];
    char* a32[3] = { smem + OFF_A32, smem + OFF_A32 + A32_STAGE, smem + OFF_A32 + 2 * A32_STAGE };
    char* a16[2] = { smem + OFF_A16, smem + OFF_A16 + A16_STAGE };
    half* sB[3]  = { (half*)(smem + OFF_B), (half*)(smem + OFF_B + B_STAGE),
                     (half*)(smem + OFF_B + 2 * B_STAGE) };
    float* sC    = (float*)smem;

    uint32_t a32u[3], sBu[3];
    #pragma unroll
    for (int i = 0; i < 3; i++) {
        a32u[i] = (uint32_t)__cvta_generic_to_shared(a32[i]);
        sBu[i]  = (uint32_t)__cvta_generic_to_shared(sB[i]);
    }

    const int tid   = threadIdx.x;
    const int wid   = tid >> 5;
    const int mtile = blockIdx.x;          // 0..31
    const int nbot  = blockIdx.y;          // 0..127
    const int nb    = nbot >> 1;
    const int ot    = nbot & 1;

    const int warp_m = wid & 3;            // 4 x 32 rows
    const int warp_n = wid >> 1 >> 1;      // 2 x 64 cols  (wid>>2)

    const float* xBase = x + (size_t)mtile * BM * DIN + (size_t)nb * IB;
    const half*  wBase = w16_g + (size_t)nb * OB * IB + (size_t)(ot * BN) * IB;

    // cp.async chunk assignments
    // A32: 128 rows x 8 x 16B = 1024 chunks -> 4/thread
    int aR[4], aC[4];
    #pragma unroll
    for (int v = 0; v < 4; v++) { int lin = v * THREADS + tid; aR[v] = lin >> 3; aC[v] = lin & 7; }
    // B: 128 rows x 4 x 16B = 512 chunks -> 2/thread
    int bN[2], bC[2];
    #pragma unroll
    for (int v = 0; v < 2; v++) { int lin = v * THREADS + tid; bN[v] = lin >> 2; bC[v] = lin & 3; }

    #define ISSUE_A(st) do { const int _b = (st) % 3; const int _k0 = (st) * BK;      \
        _Pragma("unroll")                                                             \
        for (int v = 0; v < 4; v++)                                                   \
            cp16(a32u[_b] + aR[v] * A32_STRIDE + aC[v] * 16,                          \
                 xBase + (size_t)aR[v] * DIN + _k0 + aC[v] * 4); } while (0)
    #define ISSUE_B(st) do { const int _b = (st) % 3; const int _k0 = (st) * BK;      \
        _Pragma("unroll")                                                             \
        for (int v = 0; v < 2; v++)                                                   \
            cp16(sBu[_b] + bN[v] * 80 + bC[v] * 16,                                   \
                 wBase + (size_t)bN[v] * IB + _k0 + bC[v] * 8); } while (0)

    wmma::fragment<wmma::accumulator, 16, 16, 16, float> acc[2][4];
    #pragma unroll
    for (int i = 0; i < 2; i++)
        #pragma unroll
        for (int j = 0; j < 4; j++)
            wmma::fill_fragment(acc[i][j], 0.0f);

    // ---- Prologue: groups {A0,B0}, {A1,B1}, {A2}; drain first two; convert stage0 ----
    ISSUE_A(0); ISSUE_B(0); COMMIT();
    ISSUE_A(1); ISSUE_B(1); COMMIT();
    ISSUE_A(2);             COMMIT();
    WAITG1();
    __syncthreads();                     // cp.async data visible to all threads
    convertA(a32[0], a16[0], tid);
    __syncthreads();                     // A16[0] visible before MMA

    // ---- Mainloop ----
    #pragma unroll
    for (int it = 0; it < NSTAGES; it++) {
        const int s16 = it & 1;
        const int sb  = it % 3;
        const half* A = (const half*)a16[s16];
        const half* B = sB[sb];

        // kk = 0
        {
            wmma::fragment<wmma::matrix_a, 16, 16, 16, half, wmma::row_major> af[2];
            #pragma unroll
            for (int i = 0; i < 2; i++)
                wmma::load_matrix_sync(af[i], &A[(warp_m * 32 + i * 16) * LDAH], LDAH);
            #pragma unroll
            for (int j = 0; j < 4; j++) {
                wmma::fragment<wmma::matrix_b, 16, 16, 16, half, wmma::col_major> bf;
                wmma::load_matrix_sync(bf, &B[(warp_n * 64 + j * 16) * LDAH], LDAH);
                wmma::mma_sync(acc[0][j], af[0], bf, acc[0][j]);
                wmma::mma_sync(acc[1][j], af[1], bf, acc[1][j]);
            }
        }

        // Convert next A stage while this warp's kk0 HMMAs drain
        if (it + 1 < NSTAGES)
            convertA(a32[(it + 1) % 3], a16[(it + 1) & 1], tid);

        // kk = 16
        {
            wmma::fragment<wmma::matrix_a, 16, 16, 16, half, wmma::row_major> af[2];
            #pragma unroll
            for (int i = 0; i < 2; i++)
                wmma::load_matrix_sync(af[i], &A[(warp_m * 32 + i * 16) * LDAH + 16], LDAH);
            #pragma unroll
            for (int j = 0; j < 4; j++) {
                wmma::fragment<wmma::matrix_b, 16, 16, 16, half, wmma::col_major> bf;
                wmma::load_matrix_sync(bf, &B[(warp_n * 64 + j * 16) * LDAH + 16], LDAH);
                wmma::mma_sync(acc[0][j], af[0], bf, acc[0][j]);
                wmma::mma_sync(acc[1][j], af[1], bf, acc[1][j]);
            }
        }

        // Issue group {A(it+3), B(it+2)} (buffers last touched >=1 barrier ago)
        {
            bool grp = false;
            if (it + 3 < NSTAGES) { ISSUE_A(it + 3); grp = true; }
            if (it + 2 < NSTAGES) { ISSUE_B(it + 2); grp = true; }
            if (grp) COMMIT();
        }
        // Drain everything needed for iter it+1: keep only the just-issued group
        if (it <= 5) { WAITG1(); } else { WAITG0(); }
        if (it + 1 < NSTAGES) __syncthreads();
    }

    // ---- Epilogue: stage C through shared (aliases load buffers) ----
    __syncthreads();
    #pragma unroll
    for (int i = 0; i < 2; i++)
        #pragma unroll
        for (int j = 0; j < 4; j++)
            wmma::store_matrix_sync(&sC[(warp_m * 32 + i * 16) * LDC + warp_n * 64 + j * 16],
                                    acc[i][j], LDC, wmma::mem_row_major);
    __syncthreads();

    const float* biasBase = bias + (size_t)nb * OB + ot * BN;
    float* outBase = out + (size_t)(mtile * BM) * DOUT + (size_t)nb * OB + ot * BN;

    #pragma unroll
    for (int v = 0; v < 16; v++) {
        int lin = v * THREADS + tid;
        int r   = lin >> 5;       // 0..127
        int c4  = lin & 31;       // 0..31
        float4 val = *(float4*)(&sC[r * LDC + c4 * 4]);
        float4 bv  = *(const float4*)(biasBase + c4 * 4);
        val.x += bv.x; val.y += bv.y; val.z += bv.z; val.w += bv.w;
        *(float4*)(outBase + (size_t)r * DOUT + c4 * 4) = val;
    }
}

extern "C" void kernel_launch(void* const* d_in, const int* in_sizes, int n_in,
                              void* d_out, int out_size)
{
    const float* x    = (const float*)d_in[0];
    const float* w    = (const float*)d_in[1];
    const float* bias = (const float*)d_in[2];
    float* out        = (float*)d_out;

    cudaFuncSetAttribute(block_linear_fp16_kernel,
                         cudaFuncAttributeMaxDynamicSharedMemorySize, SMEM_TOTAL);

    // Prepass: convert weights to fp16
    convert_w_kernel<<<2048, 256>>>(w);

    dim3 grid(BATCH / BM, NB * (OB / BN));   // (32, 128) = 4096 CTAs
    block_linear_fp16_kernel<<<grid, THREADS, SMEM_TOTAL>>>(x, bias, out);
}